// round 4
// baseline (speedup 1.0000x reference)
#include <cuda_runtime.h>
#include <cuda_bf16.h>
#include <cstdint>
#include <cstddef>

// ---------------------------------------------------------------------------
// BinaryConv2d forward:
//   x -> (x*rd_k+rd_b) -> sign -> 3x3 conv with (scaling[oc]*sign(w))
//     -> +pb0 -> PReLU -> +pb1 -> +x
// B=16, C=64, H=W=256. Output fp32 NCHW.
//
// Baseline sm_100 target (no tcgen05). Conv computed exactly with int8
// mma.sync.m16n8k32 (activations/weights in {-1,0,+1}), s32 accumulate,
// per-oc scaling + epilogue in fp32.
// ---------------------------------------------------------------------------

#define C_CH   64
#define IMG    256
#define HWSZ   (IMG*IMG)
#define TILE_W 128
#define KTOT   576              // 9 taps * 64 ic

// ---- smem layout (bytes). ACT and EPI share the same region (disjoint
//      lifetimes: ACT dies after the MMA mainloop, EPI born after it). -------
#define ACT_PIX_STRIDE 80       // 64 ic bytes padded to 80 (conflict-free frags)
#define ACT_ROW_STRIDE (130*ACT_PIX_STRIDE)       // 10400
#define ACT_BYTES      (3*ACT_ROW_STRIDE)         // 31200
#define EPI_PIX_STRIDE 65                         // words, padded from 64
#define EPI_BYTES      (128*EPI_PIX_STRIDE*4)     // 33280
#define SMEM_ACT  0
#define SMEM_EPI  0                               // union with ACT
#define SMEM_B    33280                           // 128-aligned, > max(ACT,EPI)
#define B_OC_STRIDE 592                           // 576 padded
#define B_BYTES   (64*B_OC_STRIDE)                // 37888
#define SMEM_PAR  (SMEM_B + B_BYTES)              // 71168
#define SMEM_TOTAL (SMEM_PAR + 1024)              // 72192  (3 CTAs/SM fit)

static __device__ __align__(16) int8_t gW[64 * KTOT];   // [oc][tap*64+ic]
static __device__ float gScaling[C_CH];

// ---------------------------------------------------------------------------
// Pre-kernel: binarize weights, reorder to [oc][tap][ic], per-oc mean|w|
// conv_w: [oc][ic][kh][kw], j = ic*9 + kh*3 + kw
// ---------------------------------------------------------------------------
__global__ void prep_weights_kernel(const float* __restrict__ w) {
    __shared__ float red[576];
    int oc = blockIdx.x;
    int j  = threadIdx.x;              // 0..575
    float v = w[oc * 576 + j];
    red[j] = fabsf(v);
    int ic  = j / 9;
    int tap = j - ic * 9;              // kh*3+kw
    int8_t s = (v > 0.f) ? 1 : ((v < 0.f) ? -1 : 0);
    gW[oc * KTOT + tap * 64 + ic] = s;
    __syncthreads();
    if (j < 32) {
        float a = 0.f;
        for (int i = j; i < 576; i += 32) a += red[i];
        #pragma unroll
        for (int o = 16; o > 0; o >>= 1) a += __shfl_down_sync(0xffffffffu, a, o);
        if (j == 0) gScaling[oc] = a * (1.0f / 576.0f);
    }
}

// ---------------------------------------------------------------------------
__device__ __forceinline__ void mma_s8(int32_t* c, uint32_t a0, uint32_t a1,
                                       uint32_t a2, uint32_t a3,
                                       uint32_t b0, uint32_t b1) {
    asm volatile(
        "mma.sync.aligned.m16n8k32.row.col.s32.s8.s8.s32 "
        "{%0,%1,%2,%3}, {%4,%5,%6,%7}, {%8,%9}, {%0,%1,%2,%3};"
        : "+r"(c[0]), "+r"(c[1]), "+r"(c[2]), "+r"(c[3])
        : "r"(a0), "r"(a1), "r"(a2), "r"(a3), "r"(b0), "r"(b1));
}

// ---------------------------------------------------------------------------
// Main kernel: CTA = (128-wide strip, h, b). 256 threads = 8 warps.
// GEMM: M=128 pixels, N=64 oc, K=576. Warp w owns M rows [16w, 16w+16).
// ---------------------------------------------------------------------------
__global__ void __launch_bounds__(256) binconv_kernel(
    const float* __restrict__ x,
    const float* __restrict__ rdk,
    const float* __restrict__ rdb,
    const float* __restrict__ pb0,
    const float* __restrict__ prw,
    const float* __restrict__ pb1,
    float* __restrict__ out)
{
    extern __shared__ __align__(128) char smem[];
    const int tid  = threadIdx.x;
    const int wid  = tid >> 5;
    const int lane = tid & 31;
    const int w0   = blockIdx.x * TILE_W;
    const int h    = blockIdx.y;
    const int b    = blockIdx.z;

    char* act = smem + SMEM_ACT;
    char* Bsm = smem + SMEM_B;
    int32_t* epi = reinterpret_cast<int32_t*>(smem + SMEM_EPI);
    float* par = reinterpret_cast<float*>(smem + SMEM_PAR);

    // ---- load weights into smem ([oc][592] padded) -------------------------
    {
        const uint32_t* src = reinterpret_cast<const uint32_t*>(gW);
        for (int i = tid; i < 64 * (KTOT / 4); i += 256) {
            int oc = i / (KTOT / 4);
            int wd = i - oc * (KTOT / 4);
            reinterpret_cast<uint32_t*>(Bsm + oc * B_OC_STRIDE)[wd] =
                src[oc * (KTOT / 4) + wd];
        }
    }
    // ---- epilogue params ---------------------------------------------------
    if (tid < 64) {
        par[tid]       = gScaling[tid];
        par[64 + tid]  = pb0[tid];
        par[128 + tid] = prw[tid];
        par[192 + tid] = pb1[tid];
    }

    // ---- binarize activations: act[r][col][ic], r=0..2 (h-1..h+1),
    //      col=0..129 (w0-1..w0+128), 80B per-pixel stride --------------------
    for (int p = tid; p < 390; p += 256) {
        int r   = p / 130;
        int col = p - r * 130;
        int ih  = h - 1 + r;
        int iw  = w0 - 1 + col;
        char* dst = act + r * ACT_ROW_STRIDE + col * ACT_PIX_STRIDE;
        if (ih >= 0 && ih < IMG && iw >= 0 && iw < IMG) {
            const float* xp = x + (size_t)b * C_CH * HWSZ + (size_t)ih * IMG + iw;
            #pragma unroll
            for (int c = 0; c < 64; c += 4) {
                uint32_t pk = 0;
                #pragma unroll
                for (int q = 0; q < 4; q++) {
                    float a = __ldg(xp + (size_t)(c + q) * HWSZ) * __ldg(rdk + c + q)
                              + __ldg(rdb + c + q);
                    uint32_t sv = (a > 0.f) ? 0x01u : ((a < 0.f) ? 0xFFu : 0x00u);
                    pk |= sv << (8 * q);
                }
                *reinterpret_cast<uint32_t*>(dst + c) = pk;
            }
        } else {
            #pragma unroll
            for (int c = 0; c < 64; c += 4)
                *reinterpret_cast<uint32_t*>(dst + c) = 0u;
        }
    }
    __syncthreads();

    // ---- MMA mainloop ------------------------------------------------------
    int32_t acc[8][4];
    #pragma unroll
    for (int nb = 0; nb < 8; nb++)
        #pragma unroll
        for (int i = 0; i < 4; i++) acc[nb][i] = 0;

    const int mrow = (wid << 4) + (lane >> 2);   // local pixel for rows 0..7
    const int icq  = 4 * (lane & 3);

    #pragma unroll
    for (int tap = 0; tap < 9; tap++) {
        const int kh = tap / 3, kw = tap - 3 * kh;
        const char* abase = act + kh * ACT_ROW_STRIDE
                          + (mrow + kw) * ACT_PIX_STRIDE + icq;
        #pragma unroll
        for (int half = 0; half < 2; half++) {
            const char* ap = abase + half * 32;
            uint32_t a0 = *reinterpret_cast<const uint32_t*>(ap);
            uint32_t a2 = *reinterpret_cast<const uint32_t*>(ap + 16);
            uint32_t a1 = *reinterpret_cast<const uint32_t*>(ap + 8 * ACT_PIX_STRIDE);
            uint32_t a3 = *reinterpret_cast<const uint32_t*>(ap + 8 * ACT_PIX_STRIDE + 16);
            const char* bbase = Bsm + (lane >> 2) * B_OC_STRIDE
                              + tap * 64 + half * 32 + icq;
            #pragma unroll
            for (int nb = 0; nb < 8; nb++) {
                const char* bp = bbase + nb * 8 * B_OC_STRIDE;
                uint32_t b0 = *reinterpret_cast<const uint32_t*>(bp);
                uint32_t b1 = *reinterpret_cast<const uint32_t*>(bp + 16);
                mma_s8(acc[nb], a0, a1, a2, a3, b0, b1);
            }
        }
    }

    // ---- EPI overlaps ACT: all warps must finish reading act first ---------
    __syncthreads();

    // ---- stage accumulators to smem [pixel][oc] (padded stride 65) ---------
    {
        const int oc0 = 2 * (lane & 3);
        #pragma unroll
        for (int nb = 0; nb < 8; nb++) {
            int oc = nb * 8 + oc0;
            epi[mrow * EPI_PIX_STRIDE + oc]           = acc[nb][0];
            epi[mrow * EPI_PIX_STRIDE + oc + 1]       = acc[nb][1];
            epi[(mrow + 8) * EPI_PIX_STRIDE + oc]     = acc[nb][2];
            epi[(mrow + 8) * EPI_PIX_STRIDE + oc + 1] = acc[nb][3];
        }
    }
    __syncthreads();

    // ---- epilogue: scale/bias/prelu/bias + residual, coalesced stores ------
    const size_t base = (size_t)b * C_CH * HWSZ + (size_t)h * IMG + w0;
    #pragma unroll
    for (int i = tid; i < 64 * TILE_W; i += 256) {
        int oc  = i >> 7;
        int pix = i & 127;
        float f = (float)epi[pix * EPI_PIX_STRIDE + oc];
        f = f * par[oc] + par[64 + oc];
        f = (f >= 0.f) ? f : (par[128 + oc] * f);
        f += par[192 + oc];
        size_t idx = base + (size_t)oc * HWSZ + pix;
        f += __ldg(x + idx);
        out[idx] = f;
    }
}

// ---------------------------------------------------------------------------
extern "C" void kernel_launch(void* const* d_in, const int* in_sizes, int n_in,
                              void* d_out, int out_size) {
    (void)in_sizes; (void)n_in; (void)out_size;
    const float* x     = (const float*)d_in[0];
    const float* rdk   = (const float*)d_in[1];
    const float* rdb   = (const float*)d_in[2];
    /* beta (d_in[3]) does not affect the STE forward pass */
    const float* convw = (const float*)d_in[4];
    const float* pb0   = (const float*)d_in[5];
    const float* prw   = (const float*)d_in[6];
    const float* pb1   = (const float*)d_in[7];
    float* out = (float*)d_out;

    prep_weights_kernel<<<64, 576>>>(convw);

    cudaFuncSetAttribute(binconv_kernel,
                         cudaFuncAttributeMaxDynamicSharedMemorySize, SMEM_TOTAL);
    dim3 grid(IMG / TILE_W, IMG, 16);   // (2, 256, 16) = 8192 CTAs
    binconv_kernel<<<grid, 256, SMEM_TOTAL>>>(x, rdk, rdb, pb0, prw, pb1, out);
}

// round 7
// speedup vs baseline: 1.3844x; 1.3844x over previous
#include <cuda_runtime.h>
#include <cuda_bf16.h>
#include <cstdint>
#include <cstddef>

// ---------------------------------------------------------------------------
// BinaryConv2d forward:
//   x -> (x*rd_k+rd_b) -> sign -> 3x3 conv with (scaling[oc]*sign(w))
//     -> +pb0 -> PReLU -> +pb1 -> +x
// B=16, C=64, H=W=256. Output fp32 NCHW.
//
// Split pipeline, 2-bit packed activations (16.8 MB scratch):
//   K1: binarize NCHW fp32 -> per-pixel {pos,neg} bitplanes (uint4/pixel).
//   K2: LUT-expand to s8 in smem, exact int8 mma.sync.m16n8k32 conv,
//       fp32 epilogue (scaling/bias/PReLU/bias) + residual.
// ---------------------------------------------------------------------------

#define C_CH   64
#define IMG    256
#define HWSZ   (IMG*IMG)
#define TILE_W 128
#define KTOT   576              // 9 taps * 64 ic

// ---- K2 smem layout (bytes). ACT and EPI union (disjoint lifetimes). ------
#define ACT_PIX_STRIDE 80       // 64 ic bytes padded to 80 (conflict-free frags)
#define ACT_ROW_STRIDE (130*ACT_PIX_STRIDE)       // 10400
#define EPI_PIX_STRIDE 65                         // words, padded from 64
#define EPI_BYTES      (128*EPI_PIX_STRIDE*4)     // 33280
#define SMEM_ACT  0
#define SMEM_EPI  0                               // union with ACT
#define SMEM_B    33280
#define B_OC_STRIDE 592                           // 576 padded
#define B_BYTES   (64*B_OC_STRIDE)                // 37888
#define SMEM_PAR  (SMEM_B + B_BYTES)              // 71168: 256 floats
#define SMEM_LUT  (SMEM_PAR + 1024)               // 72192: 256 uint32
#define SMEM_TOTAL (SMEM_LUT + 1024)              // 73216  (3 CTAs/SM)

static __device__ __align__(16) int8_t gW[64 * KTOT];   // [oc][tap*64+ic]
static __device__ float gScaling[C_CH];
// Packed sign activations: per pixel uint4 {pos(ch0-31), pos(ch32-63),
// neg(ch0-31), neg(ch32-63)}; pixel index = (b*256+h)*256+w.  16.78 MB.
static __device__ uint4 gPack[16 * IMG * IMG];

// ---------------------------------------------------------------------------
// Pre-kernel: binarize weights, reorder to [oc][tap][ic], per-oc mean|w|
// conv_w: [oc][ic][kh][kw], j = ic*9 + kh*3 + kw
// ---------------------------------------------------------------------------
__global__ void prep_weights_kernel(const float* __restrict__ w) {
    __shared__ float red[576];
    int oc = blockIdx.x;
    int j  = threadIdx.x;              // 0..575
    float v = w[oc * 576 + j];
    red[j] = fabsf(v);
    int ic  = j / 9;
    int tap = j - ic * 9;              // kh*3+kw
    int8_t s = (v > 0.f) ? 1 : ((v < 0.f) ? -1 : 0);
    gW[oc * KTOT + tap * 64 + ic] = s;
    __syncthreads();
    if (j < 32) {
        float a = 0.f;
        for (int i = j; i < 576; i += 32) a += red[i];
        #pragma unroll
        for (int o = 16; o > 0; o >>= 1) a += __shfl_down_sync(0xffffffffu, a, o);
        if (j == 0) gScaling[oc] = a * (1.0f / 576.0f);
    }
}

// ---------------------------------------------------------------------------
// K1: binarize + bitpack. CTA = (h, b), 256 threads, thread = w.
// For each channel the CTA reads one contiguous 1 KB row slice (coalesced);
// each thread accumulates its pixel's pos/neg bitmasks; one uint4 store.
// ---------------------------------------------------------------------------
__global__ void __launch_bounds__(256) pack_kernel(
    const float* __restrict__ x,
    const float* __restrict__ rdk,
    const float* __restrict__ rdb)
{
    __shared__ float sk[64], so[64];
    const int tid = threadIdx.x;
    const int h   = blockIdx.x;
    const int b   = blockIdx.y;
    if (tid < 64) { sk[tid] = rdk[tid]; so[tid] = rdb[tid]; }
    __syncthreads();

    const float* xp = x + (size_t)b * C_CH * HWSZ + (size_t)h * IMG + tid;
    uint32_t p0 = 0, p1 = 0, n0 = 0, n1 = 0;
    #pragma unroll
    for (int c = 0; c < 32; c++) {
        float a = xp[(size_t)c * HWSZ] * sk[c] + so[c];
        p0 |= (a > 0.f ? 1u : 0u) << c;
        n0 |= (a < 0.f ? 1u : 0u) << c;
    }
    #pragma unroll
    for (int c = 0; c < 32; c++) {
        float a = xp[(size_t)(c + 32) * HWSZ] * sk[c + 32] + so[c + 32];
        p1 |= (a > 0.f ? 1u : 0u) << c;
        n1 |= (a < 0.f ? 1u : 0u) << c;
    }
    gPack[((size_t)b * IMG + h) * IMG + tid] = make_uint4(p0, p1, n0, n1);
}

// ---------------------------------------------------------------------------
__device__ __forceinline__ void mma_s8(int32_t* c, uint32_t a0, uint32_t a1,
                                       uint32_t a2, uint32_t a3,
                                       uint32_t b0, uint32_t b1) {
    asm volatile(
        "mma.sync.aligned.m16n8k32.row.col.s32.s8.s8.s32 "
        "{%0,%1,%2,%3}, {%4,%5,%6,%7}, {%8,%9}, {%0,%1,%2,%3};"
        : "+r"(c[0]), "+r"(c[1]), "+r"(c[2]), "+r"(c[3])
        : "r"(a0), "r"(a1), "r"(a2), "r"(a3), "r"(b0), "r"(b1));
}

// ---------------------------------------------------------------------------
// K2: conv. CTA = (128-w strip, h, b). 256 threads = 8 warps.
// GEMM: M=128 pixels, N=64 oc, K=576. Warp w owns M rows [16w, 16w+16).
// ---------------------------------------------------------------------------
__global__ void __launch_bounds__(256) binconv_kernel(
    const float* __restrict__ x,
    const float* __restrict__ pb0,
    const float* __restrict__ prw,
    const float* __restrict__ pb1,
    float* __restrict__ out)
{
    extern __shared__ __align__(128) char smem[];
    const int tid  = threadIdx.x;
    const int wid  = tid >> 5;
    const int lane = tid & 31;
    const int w0   = blockIdx.x * TILE_W;
    const int h    = blockIdx.y;
    const int b    = blockIdx.z;

    char* act = smem + SMEM_ACT;
    char* Bsm = smem + SMEM_B;
    int32_t* epi = reinterpret_cast<int32_t*>(smem + SMEM_EPI);
    float* par = reinterpret_cast<float*>(smem + SMEM_PAR);
    uint32_t* lut = reinterpret_cast<uint32_t*>(smem + SMEM_LUT);

    // ---- weights into smem ([oc][592] padded) ------------------------------
    {
        const uint32_t* src = reinterpret_cast<const uint32_t*>(gW);
        for (int i = tid; i < 64 * (KTOT / 4); i += 256) {
            int oc = i / (KTOT / 4);
            int wd = i - oc * (KTOT / 4);
            reinterpret_cast<uint32_t*>(Bsm + oc * B_OC_STRIDE)[wd] =
                src[oc * (KTOT / 4) + wd];
        }
    }
    // ---- epilogue params + nibble->byte4 LUT -------------------------------
    if (tid < 64) {
        par[tid]       = gScaling[tid];
        par[64 + tid]  = pb0[tid];
        par[128 + tid] = prw[tid];
        par[192 + tid] = pb1[tid];
    }
    {
        const uint32_t pos = tid & 0xFu, neg = tid >> 4;   // tid < 256
        uint32_t wv = 0;
        #pragma unroll
        for (int k = 0; k < 4; k++) {
            uint32_t byte = ((pos >> k) & 1u) ? 0x01u
                          : (((neg >> k) & 1u) ? 0xFFu : 0x00u);
            wv |= byte << (8 * k);
        }
        lut[tid] = wv;
    }
    __syncthreads();

    // ---- act halo: 390 pixels, 1 uint4 load + LUT expand + 4 STS.128 -------
    for (int i = tid; i < 390; i += 256) {
        const int r   = i / 130;
        const int col = i - r * 130;
        const int ih  = h - 1 + r;
        const int iw  = w0 - 1 + col;
        char* dst = act + r * ACT_ROW_STRIDE + col * ACT_PIX_STRIDE;
        if (ih >= 0 && ih < IMG && iw >= 0 && iw < IMG) {
            const uint4 pk = gPack[((size_t)b * IMG + ih) * IMG + iw];
            uint32_t wb[16];
            #pragma unroll
            for (int j = 0; j < 8; j++) {
                wb[j]     = lut[((pk.x >> (4 * j)) & 0xFu) |
                                (((pk.z >> (4 * j)) & 0xFu) << 4)];
                wb[j + 8] = lut[((pk.y >> (4 * j)) & 0xFu) |
                                (((pk.w >> (4 * j)) & 0xFu) << 4)];
            }
            #pragma unroll
            for (int q = 0; q < 4; q++)
                *reinterpret_cast<uint4*>(dst + q * 16) =
                    make_uint4(wb[4*q], wb[4*q+1], wb[4*q+2], wb[4*q+3]);
        } else {
            #pragma unroll
            for (int q = 0; q < 4; q++)
                *reinterpret_cast<uint4*>(dst + q * 16) =
                    make_uint4(0u, 0u, 0u, 0u);
        }
    }
    __syncthreads();

    // ---- MMA mainloop ------------------------------------------------------
    int32_t acc[8][4];
    #pragma unroll
    for (int nb = 0; nb < 8; nb++)
        #pragma unroll
        for (int i = 0; i < 4; i++) acc[nb][i] = 0;

    const int mrow = (wid << 4) + (lane >> 2);   // local pixel for rows 0..7
    const int icq  = 4 * (lane & 3);

    #pragma unroll
    for (int tap = 0; tap < 9; tap++) {
        const int kh = tap / 3, kw = tap - 3 * kh;
        const char* abase = act + kh * ACT_ROW_STRIDE
                          + (mrow + kw) * ACT_PIX_STRIDE + icq;
        #pragma unroll
        for (int half = 0; half < 2; half++) {
            const char* ap = abase + half * 32;
            uint32_t a0 = *reinterpret_cast<const uint32_t*>(ap);
            uint32_t a2 = *reinterpret_cast<const uint32_t*>(ap + 16);
            uint32_t a1 = *reinterpret_cast<const uint32_t*>(ap + 8 * ACT_PIX_STRIDE);
            uint32_t a3 = *reinterpret_cast<const uint32_t*>(ap + 8 * ACT_PIX_STRIDE + 16);
            const char* bbase = Bsm + (lane >> 2) * B_OC_STRIDE
                              + tap * 64 + half * 32 + icq;
            #pragma unroll
            for (int nb = 0; nb < 8; nb++) {
                const char* bp = bbase + nb * 8 * B_OC_STRIDE;
                uint32_t b0 = *reinterpret_cast<const uint32_t*>(bp);
                uint32_t b1 = *reinterpret_cast<const uint32_t*>(bp + 16);
                mma_s8(acc[nb], a0, a1, a2, a3, b0, b1);
            }
        }
    }

    // ---- EPI overlaps ACT: all warps finish reading act first --------------
    __syncthreads();

    {
        const int oc0 = 2 * (lane & 3);
        #pragma unroll
        for (int nb = 0; nb < 8; nb++) {
            int oc = nb * 8 + oc0;
            epi[mrow * EPI_PIX_STRIDE + oc]           = acc[nb][0];
            epi[mrow * EPI_PIX_STRIDE + oc + 1]       = acc[nb][1];
            epi[(mrow + 8) * EPI_PIX_STRIDE + oc]     = acc[nb][2];
            epi[(mrow + 8) * EPI_PIX_STRIDE + oc + 1] = acc[nb][3];
        }
    }
    __syncthreads();

    // ---- epilogue: scale/bias/prelu/bias + residual, coalesced stores ------
    const size_t base = (size_t)b * C_CH * HWSZ + (size_t)h * IMG + w0;
    #pragma unroll
    for (int i = tid; i < 64 * TILE_W; i += 256) {
        int oc  = i >> 7;
        int pix = i & 127;
        float f = (float)epi[pix * EPI_PIX_STRIDE + oc];
        f = f * par[oc] + par[64 + oc];
        f = (f >= 0.f) ? f : (par[128 + oc] * f);
        f += par[192 + oc];
        size_t idx = base + (size_t)oc * HWSZ + pix;
        f += __ldg(x + idx);
        out[idx] = f;
    }
}

// ---------------------------------------------------------------------------
extern "C" void kernel_launch(void* const* d_in, const int* in_sizes, int n_in,
                              void* d_out, int out_size) {
    (void)in_sizes; (void)n_in; (void)out_size;
    const float* x     = (const float*)d_in[0];
    const float* rdk   = (const float*)d_in[1];
    const float* rdb   = (const float*)d_in[2];
    /* beta (d_in[3]) does not affect the STE forward pass */
    const float* convw = (const float*)d_in[4];
    const float* pb0   = (const float*)d_in[5];
    const float* prw   = (const float*)d_in[6];
    const float* pb1   = (const float*)d_in[7];
    float* out = (float*)d_out;

    prep_weights_kernel<<<64, 576>>>(convw);
    pack_kernel<<<dim3(IMG, 16), 256>>>(x, rdk, rdb);

    cudaFuncSetAttribute(binconv_kernel,
                         cudaFuncAttributeMaxDynamicSharedMemorySize, SMEM_TOTAL);
    dim3 grid(IMG / TILE_W, IMG, 16);   // (2, 256, 16) = 8192 CTAs
    binconv_kernel<<<grid, 256, SMEM_TOTAL>>>(x, pb0, prw, pb1, out);
}